// round 6
// baseline (speedup 1.0000x reference)
#include <cuda_runtime.h>
#include <cstdint>

// SparseBMM: C[b] = A[b] @ B[b]
//  A: [8, 4096, 4096] f32, ~80% of 128x128 tiles exactly zero
//  B: [8, 4096, 128] f32;  C: [8, 4096, 128] f32
//
// Round 6: round-1 compute core (pure FFMA2, ~85 live regs, no spills)
// + cp.async double-buffered A stream (A never occupies registers).
// Zero steps skip B staging and all math. KT=32 -> 32KB smem, 4 CTAs/SM.

#define BATCHES 8
#define MDIM    4096
#define KDIM    4096
#define NDIM    128
#define MT      64
#define KT      32
#define KSTEPS  (KDIM / KT)     // 128
#define NTHREADS 128

#define A_TILE  (MT * KT)       // 2048 floats = 8KB
#define B_TILE  (KT * NDIM)     // 4096 floats = 16KB
#define SMEM_FLOATS (2 * A_TILE + B_TILE)
#define SMEM_BYTES  (SMEM_FLOATS * 4)   // 32KB

__device__ __forceinline__ void cp_async16(uint32_t dst_smem, const float* src) {
    asm volatile("cp.async.cg.shared.global [%0], [%1], 16;"
                 :: "r"(dst_smem), "l"(src));
}
__device__ __forceinline__ void cp_commit() {
    asm volatile("cp.async.commit_group;");
}
__device__ __forceinline__ void cp_wait_1() {
    asm volatile("cp.async.wait_group 1;");
}

__global__ __launch_bounds__(NTHREADS, 4)
void sparse_bmm_kernel(const float* __restrict__ A,
                       const float* __restrict__ B,
                       float* __restrict__ C) {
    extern __shared__ float sm[];
    float* A0 = sm;                  // A buffer 0: [64][32] f32
    float* A1 = sm + A_TILE;         // A buffer 1
    float* Bs = sm + 2 * A_TILE;     // B tile: [32][128] f32

    const int bidx  = blockIdx.x;    // 0..511
    const int batch = bidx >> 6;
    const int mt    = bidx & 63;

    const float* Ag = A + (size_t)batch * MDIM * KDIM + (size_t)mt * MT * KDIM;
    const float* Bg = B + (size_t)batch * KDIM * NDIM;
    float*       Cg = C + (size_t)batch * MDIM * NDIM + (size_t)mt * MT * NDIM;

    const int tid = threadIdx.x;
    const int tx  = tid & 15;        // 8 output cols each
    const int ty  = tid >> 4;        // 8 output rows each

    // cp.async geometry: 512 16B-chunks per A tile (64 rows x 8 chunks).
    // Thread handles chunks (tid + 128*t), t<4: row = tid>>3 + 16*t, col = tid&7.
    const int arow = tid >> 3;       // base row 0..15
    const int acol = tid & 7;        // float4 column 0..7

    const uint32_t sa0 = (uint32_t)__cvta_generic_to_shared(A0);
    const uint32_t sa1 = (uint32_t)__cvta_generic_to_shared(A1);
    const uint32_t a_sm_off = (uint32_t)(arow * KT + acol * 4) * 4;
    const float*   a_gm     = Ag + (size_t)arow * KDIM + acol * 4;

    unsigned long long acc[8][4];
#pragma unroll
    for (int i = 0; i < 8; i++)
#pragma unroll
        for (int p = 0; p < 4; p++) acc[i][p] = 0ull;

    // ---- prologue: async-load tile 0 into A0 ----
#pragma unroll
    for (int t = 0; t < 4; t++)
        cp_async16(sa0 + a_sm_off + (uint32_t)(t * 16 * KT) * 4,
                   a_gm + (size_t)(t * 16) * KDIM);
    cp_commit();

    for (int kt = 0; kt < KSTEPS; kt++) {
        const float*   Acur = (kt & 1) ? A1 : A0;
        const uint32_t snxt = (kt & 1) ? sa0 : sa1;

        // ---- issue async load of tile kt+1 into the other buffer ----
        // Safe: buffer (kt+1)&1 was last READ in step kt-1 (nz-check by the
        // same thread at the same addresses, or compute ended by a barrier).
        if (kt + 1 < KSTEPS) {
            const float* src = a_gm + (size_t)(kt + 1) * KT;
#pragma unroll
            for (int t = 0; t < 4; t++)
                cp_async16(snxt + a_sm_off + (uint32_t)(t * 16 * KT) * 4,
                           src + (size_t)(t * 16) * KDIM);
        }
        cp_commit();   // one group per iteration (possibly empty) -> wait_1 exact

        // ---- tile kt is complete after wait_group 1; check own chunks ----
        cp_wait_1();
        unsigned nz = 0;
#pragma unroll
        for (int t = 0; t < 4; t++) {
            const uint4 v = *(const uint4*)(Acur + (arow + t * 16) * KT + acol * 4);
            nz |= v.x | v.y | v.z | v.w;
        }
        // Barrier: (a) all threads have waited -> whole tile visible to all;
        // (b) orders prior compute/nz reads before the next buffer overwrite.
        const int flag = __syncthreads_or(nz != 0u);

        if (flag) {
            // ---- stage B tile [32][128] (L2-resident, reused by 64 CTAs) ----
            const float4* Bsrc = (const float4*)(Bg + (size_t)kt * KT * NDIM);
            float4* Bdst = (float4*)Bs;
#pragma unroll
            for (int t = 0; t < 8; t++)
                Bdst[tid + t * NTHREADS] = Bsrc[tid + t * NTHREADS];
            __syncthreads();

            // ---- compute: round-1 core (scalar A broadcast + FFMA2) ----
            const float* ar = Acur + (ty * 8) * KT;
#pragma unroll 8
            for (int kk = 0; kk < KT; kk++) {
                unsigned long long bb[4];
                const unsigned long long* bp =
                    (const unsigned long long*)(Bs + kk * NDIM + tx * 8);
#pragma unroll
                for (int p = 0; p < 4; p++) bb[p] = bp[p];

                unsigned long long aa[8];
#pragma unroll
                for (int i = 0; i < 8; i++) {
                    float a = ar[i * KT + kk];
                    asm("mov.b64 %0, {%1, %1};" : "=l"(aa[i]) : "f"(a));
                }
#pragma unroll
                for (int i = 0; i < 8; i++)
#pragma unroll
                    for (int p = 0; p < 4; p++)
                        asm("fma.rn.f32x2 %0, %1, %2, %0;"
                            : "+l"(acc[i][p])
                            : "l"(aa[i]), "l"(bb[p]));
            }
            // Protect Acur and Bs from the next overwrite.
            __syncthreads();
        }
    }

    // ---- epilogue ----
#pragma unroll
    for (int i = 0; i < 8; i++) {
        float* crow = Cg + (size_t)(ty * 8 + i) * NDIM + tx * 8;
#pragma unroll
        for (int p = 0; p < 4; p++)
            *(unsigned long long*)(crow + p * 2) = acc[i][p];
    }
}

extern "C" void kernel_launch(void* const* d_in, const int* in_sizes, int n_in,
                              void* d_out, int out_size) {
    const float* a = (const float*)d_in[0];
    const float* b = (const float*)d_in[1];
    float* c = (float*)d_out;

    cudaFuncSetAttribute(sparse_bmm_kernel,
                         cudaFuncAttributeMaxDynamicSharedMemorySize,
                         SMEM_BYTES);

    dim3 grid(BATCHES * (MDIM / MT));   // 512 CTAs
    sparse_bmm_kernel<<<grid, NTHREADS, SMEM_BYTES>>>(a, b, c);
}